// round 10
// baseline (speedup 1.0000x reference)
#include <cuda_runtime.h>
#include <cuda_bf16.h>
#include <cstdint>

#define D_OUT 32768
#define D_IN  1024
#define MT 128            // rows per CTA
#define NTC 128           // sigma-rows (n) per chunk
#define NCH 8             // D_IN / NTC
#define KS 64             // k per SMEM stage
#define KSTEPS 16         // D_IN / KS
#define NCTA 256          // D_OUT / MT
#define THREADS 256
#define PREP_BLOCKS 2048
#define PREP_THREADS 256

// SMEM map
#define STG_A0 0
#define STG_B0 16384
#define STG_STRIDE 32768          // stage = A(16K) + B(16K)
#define EPI_W_OFF 65536           // 128 rows x 528B (512 data + 16 pad)
#define EPI_W_PITCH 528
#define EPI_D_OFF (65536 + 128 * 528)          // 133120; 128 rows x 272B
#define EPI_D_PITCH 272
#define RED_OFF (133120 + 128 * 272)           // 167936
#define SMEM_BYTES (RED_OFF + 1024)            // 168960

// ---------------- device scratch (no allocations allowed) ----------------
__device__ __align__(16) __nv_bfloat16 g_Db[33554432];   // D bf16 [32768 x 1024]
__device__ __align__(16) __nv_bfloat16 g_Sb[1048576];    // Sigma bf16 [1024 x 1024] row-major
__device__ float g_bin[PREP_BLOCKS];
__device__ float g_act[NCTA];
__device__ float g_geom[NCTA];
__device__ unsigned g_ctr = 0;

// ---------------- portable PTX helpers (no 'a'-gated features) ----------------
__device__ __forceinline__ uint32_t smem_u32(const void* p) {
    uint32_t a;
    asm("{ .reg .u64 t; cvta.to.shared.u64 t, %1; cvt.u32.u64 %0, t; }" : "=r"(a) : "l"(p));
    return a;
}
__device__ __forceinline__ void cp_async16(uint32_t dst, const void* src) {
    asm volatile("cp.async.cg.shared.global [%0], [%1], 16;" :: "r"(dst), "l"(src) : "memory");
}
#define CP_COMMIT() asm volatile("cp.async.commit_group;" ::: "memory")
#define CP_WAIT(n)  asm volatile("cp.async.wait_group %0;" :: "n"(n) : "memory")

__device__ __forceinline__ void ldsm4(uint32_t* r, uint32_t addr) {
    asm volatile("ldmatrix.sync.aligned.m8n8.x4.shared.b16 {%0,%1,%2,%3}, [%4];"
                 : "=r"(r[0]), "=r"(r[1]), "=r"(r[2]), "=r"(r[3]) : "r"(addr));
}
__device__ __forceinline__ void mma16816(float* c, const uint32_t* a, const uint32_t* b) {
    asm volatile(
        "mma.sync.aligned.m16n8k16.row.col.f32.bf16.bf16.f32 "
        "{%0,%1,%2,%3}, {%4,%5,%6,%7}, {%8,%9}, {%0,%1,%2,%3};"
        : "+f"(c[0]), "+f"(c[1]), "+f"(c[2]), "+f"(c[3])
        : "r"(a[0]), "r"(a[1]), "r"(a[2]), "r"(a[3]), "r"(b[0]), "r"(b[1]));
}
__device__ __forceinline__ uint32_t swz(uint32_t off) { return off ^ ((off >> 3) & 0x70); }
__device__ __forceinline__ float fast_tanh(float x) {
    float y;
    asm("tanh.approx.f32 %0, %1;" : "=f"(y) : "f"(x));
    return y;
}

// ---------------- kernel 1: prep (Sigma->bf16, Th, D=W-s(Q+Th) bf16, binary reg) ----------------
__global__ void __launch_bounds__(PREP_THREADS) k_prep(
    const float4* __restrict__ W4, const float4* __restrict__ Q4,
    const float* __restrict__ s, const float4* __restrict__ T4,
    const float4* __restrict__ S4)
{
    __shared__ float red[PREP_THREADS];
    unsigned gsz = gridDim.x * blockDim.x;
    unsigned gtid = blockIdx.x * blockDim.x + threadIdx.x;

    // Sigma f32 -> bf16 (262144 float4s)
    {
        __nv_bfloat162* o = reinterpret_cast<__nv_bfloat162*>(g_Sb);
        for (unsigned i = gtid; i < 262144u; i += gsz) {
            float4 v = S4[i];
            o[2 * i]     = __floats2bfloat162_rn(v.x, v.y);
            o[2 * i + 1] = __floats2bfloat162_rn(v.z, v.w);
        }
    }

    const unsigned n4 = 33554432u / 4u;
    float bin = 0.f;
    __nv_bfloat162* Db2 = reinterpret_cast<__nv_bfloat162*>(g_Db);
    for (unsigned i = gtid; i < n4; i += gsz) {
        int row = (int)(i >> 8);
        float sv = s[row];
        float4 w = W4[i], q = Q4[i], t = T4[i];
        float th0 = fminf(fmaxf(0.6f * fast_tanh(t.x) + 0.5f, 0.f), 1.f);
        float th1 = fminf(fmaxf(0.6f * fast_tanh(t.y) + 0.5f, 0.f), 1.f);
        float th2 = fminf(fmaxf(0.6f * fast_tanh(t.z) + 0.5f, 0.f), 1.f);
        float th3 = fminf(fmaxf(0.6f * fast_tanh(t.w) + 0.5f, 0.f), 1.f);
        float d0 = w.x - sv * (q.x + th0);
        float d1 = w.y - sv * (q.y + th1);
        float d2 = w.z - sv * (q.z + th2);
        float d3 = w.w - sv * (q.w + th3);
        Db2[2 * i]     = __floats2bfloat162_rn(d0, d1);
        Db2[2 * i + 1] = __floats2bfloat162_rn(d2, d3);
        float u0 = 2.f * th0 - 1.f, u1 = 2.f * th1 - 1.f;
        float u2 = 2.f * th2 - 1.f, u3 = 2.f * th3 - 1.f;
        bin += (1.f - u0 * u0) + (1.f - u1 * u1) + (1.f - u2 * u2) + (1.f - u3 * u3);
    }
    red[threadIdx.x] = bin;
    __syncthreads();
    for (int o = PREP_THREADS / 2; o > 0; o >>= 1) {
        if (threadIdx.x < o) red[threadIdx.x] += red[threadIdx.x + o];
        __syncthreads();
    }
    if (threadIdx.x == 0) g_bin[blockIdx.x] = red[0];
}

// ---------------- kernel 2: Y = D @ Sigma^T (mma.sync) + fused dots + fused final ----------------
__global__ void __launch_bounds__(THREADS, 1) k_main(const float* __restrict__ W,
                                                     float* __restrict__ out) {
    extern __shared__ __align__(16) char smem[];
    uint32_t sb = smem_u32(smem);
    int tid = threadIdx.x, lane = tid & 31, wid = tid >> 5;
    int warpM = wid & 3, warpN = wid >> 2;     // 4 x 2 warp grid: 32m x 64n per warp
    int rowBase = blockIdx.x * MT;

    const uint4* gA = reinterpret_cast<const uint4*>(g_Db) + (size_t)rowBase * (D_IN / 8);
    const uint4* gB = reinterpret_cast<const uint4*>(g_Sb);
    const uint4* gWu = reinterpret_cast<const uint4*>(W) + (size_t)rowBase * (D_IN / 4);
    const uint4* gDu = gA;

    // ldmatrix per-lane address components
    int aRow = (lane & 7) + ((lane >> 3) & 1) * 8;
    int aKb  = ((lane >> 4) & 1) * 16;
    int bRow = (lane & 7) + ((lane >> 4) & 1) * 8;
    int bKb  = ((lane >> 3) & 1) * 16;

    float pa[4] = {0.f, 0.f, 0.f, 0.f};
    float ra[4] = {0.f, 0.f, 0.f, 0.f};

    for (int nc = 0; nc < NCH; ++nc) {
        const uint4* gBn = gB + (size_t)(nc * NTC) * (D_IN / 8);

        float acc[2][8][4];
        #pragma unroll
        for (int mi = 0; mi < 2; ++mi)
            #pragma unroll
            for (int ni = 0; ni < 8; ++ni)
                #pragma unroll
                for (int e = 0; e < 4; ++e) acc[mi][ni][e] = 0.f;

        // prologue: stage 0 + epi part 0
        {
            uint32_t sA = sb + STG_A0, sB = sb + STG_B0;
            #pragma unroll
            for (int it = 0; it < 4; ++it) {
                int u = tid + it * THREADS;
                int r = u >> 3, k8 = u & 7;
                uint32_t so = swz((uint32_t)((r << 7) | (k8 << 4)));
                cp_async16(sA + so, gA  + (size_t)r * 128 + k8);
                cp_async16(sB + so, gBn + (size_t)r * 128 + k8);
            }
            {   // epi part 0: W (256 uint4), Db (128 uint4)
                int u = tid;                       // part 0 base
                int r = u >> 5, c16 = u & 31;
                cp_async16(sb + EPI_W_OFF + r * EPI_W_PITCH + c16 * 16,
                           gWu + (size_t)r * 256 + nc * 32 + c16);
                if (tid < 128) {
                    int r2 = tid >> 4, c2 = tid & 15;
                    cp_async16(sb + EPI_D_OFF + r2 * EPI_D_PITCH + c2 * 16,
                               gDu + (size_t)r2 * 128 + nc * 16 + c2);
                }
            }
            CP_COMMIT();
        }

        for (int ks = 0; ks < KSTEPS; ++ks) {
            int cur = ks & 1;
            if (ks + 1 < KSTEPS) {
                int nxt = (ks + 1) & 1;
                uint32_t sA = sb + STG_A0 + nxt * STG_STRIDE;
                uint32_t sB = sb + STG_B0 + nxt * STG_STRIDE;
                int kc = (ks + 1) * 8;
                #pragma unroll
                for (int it = 0; it < 4; ++it) {
                    int u = tid + it * THREADS;
                    int r = u >> 3, k8 = u & 7;
                    uint32_t so = swz((uint32_t)((r << 7) | (k8 << 4)));
                    cp_async16(sA + so, gA  + (size_t)r * 128 + kc + k8);
                    cp_async16(sB + so, gBn + (size_t)r * 128 + kc + k8);
                }
                {   // epi part ks+1
                    int p = ks + 1;
                    int u = p * 256 + tid;
                    int r = u >> 5, c16 = u & 31;
                    cp_async16(sb + EPI_W_OFF + r * EPI_W_PITCH + c16 * 16,
                               gWu + (size_t)r * 256 + nc * 32 + c16);
                    if (tid < 128) {
                        int u2 = p * 128 + tid;
                        int r2 = u2 >> 4, c2 = u2 & 15;
                        cp_async16(sb + EPI_D_OFF + r2 * EPI_D_PITCH + c2 * 16,
                                   gDu + (size_t)r2 * 128 + nc * 16 + c2);
                    }
                }
                CP_COMMIT();
                CP_WAIT(1);
            } else {
                CP_WAIT(0);
            }
            __syncthreads();

            uint32_t sA = sb + STG_A0 + cur * STG_STRIDE;
            uint32_t sB = sb + STG_B0 + cur * STG_STRIDE;
            #pragma unroll
            for (int kk = 0; kk < 4; ++kk) {
                uint32_t afr[2][4], bfr[4][4];
                #pragma unroll
                for (int mi = 0; mi < 2; ++mi) {
                    uint32_t off = (uint32_t)((warpM * 32 + mi * 16 + aRow) * 128 + kk * 32 + aKb);
                    ldsm4(afr[mi], sA + swz(off));
                }
                #pragma unroll
                for (int n2 = 0; n2 < 4; ++n2) {
                    uint32_t off = (uint32_t)((warpN * 64 + n2 * 16 + bRow) * 128 + kk * 32 + bKb);
                    ldsm4(bfr[n2], sB + swz(off));
                }
                #pragma unroll
                for (int mi = 0; mi < 2; ++mi)
                    #pragma unroll
                    for (int ni = 0; ni < 8; ++ni)
                        mma16816(acc[mi][ni], afr[mi], &bfr[ni >> 1][(ni & 1) * 2]);
            }
            __syncthreads();
        }

        // fold accumulators into per-row running dots, reading epi tiles from SMEM
        #pragma unroll
        for (int mi = 0; mi < 2; ++mi) {
            #pragma unroll
            for (int h = 0; h < 2; ++h) {
                int rl = warpM * 32 + mi * 16 + h * 8 + (lane >> 2);
                const float2* w2 = reinterpret_cast<const float2*>(smem + EPI_W_OFF + rl * EPI_W_PITCH);
                const __nv_bfloat162* d2 = reinterpret_cast<const __nv_bfloat162*>(smem + EPI_D_OFF + rl * EPI_D_PITCH);
                float accP = 0.f, accR = 0.f;
                #pragma unroll
                for (int ni = 0; ni < 8; ++ni) {
                    int lc2 = warpN * 32 + ni * 4 + (lane & 3);
                    float2 wv = w2[lc2];
                    float2 dv = __bfloat1622float2(d2[lc2]);
                    float y0 = acc[mi][ni][h * 2], y1 = acc[mi][ni][h * 2 + 1];
                    accP = fmaf(wv.x, y0, fmaf(wv.y, y1, accP));
                    accR = fmaf(dv.x, y0, fmaf(dv.y, y1, accR));
                }
                pa[mi * 2 + h] += accP;
                ra[mi * 2 + h] += accR;
            }
        }
        __syncthreads();   // epi buffers reusable next chunk
    }

    // deterministic per-CTA reduction
    #pragma unroll
    for (int m = 0; m < 4; ++m) {
        pa[m] += __shfl_xor_sync(0xffffffffu, pa[m], 1);
        pa[m] += __shfl_xor_sync(0xffffffffu, pa[m], 2);
        ra[m] += __shfl_xor_sync(0xffffffffu, ra[m], 1);
        ra[m] += __shfl_xor_sync(0xffffffffu, ra[m], 2);
    }
    float* sW = reinterpret_cast<float*>(smem + RED_OFF);   // per-row a_i
    float* sD = sW + 128;                                   // per-row r_i
    if (warpN == 0 && (lane & 3) == 0) {
        #pragma unroll
        for (int m = 0; m < 4; ++m) {
            int rl = warpM * 32 + (m >> 1) * 16 + (lane >> 2) + (m & 1) * 8;
            sW[rl] = pa[m];
            sD[rl] = ra[m];
        }
    }
    __syncthreads();
    if (warpN == 1 && (lane & 3) == 0) {
        #pragma unroll
        for (int m = 0; m < 4; ++m) {
            int rl = warpM * 32 + (m >> 1) * 16 + (lane >> 2) + (m & 1) * 8;
            sW[rl] += pa[m];
            sD[rl] += ra[m];
        }
    }
    __syncthreads();
    if (tid < 128) {
        float ai = sW[tid];
        sW[tid] = 4.f * ai * ai;   // geom per row
    }
    __syncthreads();
    for (int o = 64; o > 0; o >>= 1) {
        if (tid < o) { sW[tid] += sW[tid + o]; sD[tid] += sD[tid + o]; }
        __syncthreads();
    }
    if (tid == 0) {
        g_geom[blockIdx.x] = sW[0];
        g_act[blockIdx.x]  = sD[0];
    }

    // fused final: last CTA to finish combines everything (fixed order = deterministic)
    __shared__ int isLast;
    if (tid == 0) {
        __threadfence();
        unsigned prev = atomicAdd(&g_ctr, 1u);
        isLast = (prev == (unsigned)(NCTA - 1)) ? 1 : 0;
    }
    __syncthreads();
    if (isLast) {
        __threadfence();
        float b = 0.f, a = 0.f, g = 0.f;
        for (int i = tid; i < PREP_BLOCKS; i += THREADS) b += g_bin[i];
        for (int i = tid; i < NCTA; i += THREADS) { a += g_act[i]; g += g_geom[i]; }
        float* red = reinterpret_cast<float*>(smem + RED_OFF);
        red[tid] = a + 2.0e-4f * b + 0.05f * g;
        __syncthreads();
        for (int o = THREADS / 2; o > 0; o >>= 1) {
            if (tid < o) red[tid] += red[tid + o];
            __syncthreads();
        }
        if (tid == 0) {
            out[0] = red[0];
            g_ctr = 0;   // reset for next graph replay
        }
    }
}

// ---------------- launch ----------------
extern "C" void kernel_launch(void* const* d_in, const int* in_sizes, int n_in,
                              void* d_out, int out_size) {
    const float* W     = (const float*)d_in[0];
    const float* Sigma = (const float*)d_in[1];
    const float* Q     = (const float*)d_in[2];
    const float* s     = (const float*)d_in[3];
    const float* Theta = (const float*)d_in[4];
    float* out = (float*)d_out;

    cudaFuncSetAttribute(k_main, cudaFuncAttributeMaxDynamicSharedMemorySize, SMEM_BYTES);

    k_prep<<<PREP_BLOCKS, PREP_THREADS>>>(
        (const float4*)W, (const float4*)Q, s, (const float4*)Theta, (const float4*)Sigma);
    k_main<<<NCTA, THREADS, SMEM_BYTES>>>(W, out);
}